// round 14
// baseline (speedup 1.0000x reference)
#include <cuda_runtime.h>
#include <cuda_bf16.h>
#include <math.h>

// N=16384 nodes, L=8, D=256, H=256, R=64. Gate order i,f,g,o.
// Fused recurrence: gates_t = [h_{t-1} | x_t] @ [Whh | Wih]^T + b (K=512 GEMM
// per step; t=0 uses x-only K=256 since h0=0). mma.sync bf16 hi/lo split
// (3 products), XOR-swizzled smem, 3-stage cp.async pipeline.
// k_step: 512-thread CTA, tile M=256 x N=128 (27% less smem traffic/MMA,
// half the barriers/MMA vs 128x128). k_enc: 256-thread 128x128 path.

#define NT 256
#define NTS 512

// ------------------------- device scratch (no allocs) -----------------------
__device__ float g_c[8388608];               // [2][16384][256] cell state fp32
__device__ __nv_bfloat16 g_hs_hi[16777216];  // [2 lstm][2 buf][16384][256]
__device__ __nv_bfloat16 g_hs_lo[16777216];
__device__ __nv_bfloat16 g_xs_hi[67108864];  // [2 chain][16384*8 (n*8+l)][256]
__device__ __nv_bfloat16 g_xs_lo[67108864];
__device__ __nv_bfloat16 g_Wcomb_hi[1048576]; // [2][8 strip][128(g*32+jj)][512(Whh|Wih)]
__device__ __nv_bfloat16 g_Wcomb_lo[1048576];
__device__ __nv_bfloat16 g_WencS_hi[147456];  // [256][576]
__device__ __nv_bfloat16 g_WencS_lo[147456];
__device__ __nv_bfloat16 g_rels_hi[1048576];  // [16384][64]
__device__ __nv_bfloat16 g_rels_lo[1048576];
__device__ float g_bsum[2048];                // [2][1024] bih+bhh

// ------------------------------- helpers ------------------------------------
__device__ __forceinline__ float fsig(float x) {
  return __fdividef(1.0f, 1.0f + __expf(-x));
}
__device__ __forceinline__ float ftanh(float x) {
  return 2.0f * __fdividef(1.0f, 1.0f + __expf(-2.0f * x)) - 1.0f;
}

__device__ __forceinline__ void mma16816(float* d, const unsigned* a, const unsigned* b) {
  asm volatile(
      "mma.sync.aligned.m16n8k16.row.col.f32.bf16.bf16.f32 "
      "{%0,%1,%2,%3}, {%4,%5,%6,%7}, {%8,%9}, {%0,%1,%2,%3};\n"
      : "+f"(d[0]), "+f"(d[1]), "+f"(d[2]), "+f"(d[3])
      : "r"(a[0]), "r"(a[1]), "r"(a[2]), "r"(a[3]), "r"(b[0]), "r"(b[1]));
}
__device__ __forceinline__ void ldsm4(unsigned* r, const __nv_bfloat16* p) {
  unsigned a = (unsigned)__cvta_generic_to_shared(p);
  asm volatile("ldmatrix.sync.aligned.m8n8.x4.shared.b16 {%0,%1,%2,%3}, [%4];\n"
               : "=r"(r[0]), "=r"(r[1]), "=r"(r[2]), "=r"(r[3]) : "r"(a));
}
__device__ __forceinline__ void cpa16(void* dst, const void* src) {
  unsigned s = (unsigned)__cvta_generic_to_shared(dst);
  asm volatile("cp.async.cg.shared.global [%0], [%1], 16;\n" :: "r"(s), "l"(src));
}
#define CP_COMMIT asm volatile("cp.async.commit_group;\n")
template <int N>
__device__ __forceinline__ void cp_wait() {
  asm volatile("cp.async.wait_group %0;\n" :: "n"(N));
}

// XOR-swizzled smem layout: array [rows][32 bf16] (64B rows, no pad).
// Element offset for (row r, 16B-seg s in 0..3): r*32 + ((s ^ ((r>>1)&3))<<3).
#define SWZ(r, s) ((r) * 32 + ((((s) ^ (((r) >> 1) & 3))) << 3))

// --- k_step buffers (M=256): [Ahi 256x32][Alo][Bhi 128x32][Blo] = 48KB ---
#define S_AHI 0
#define S_ALO 8192
#define S_BHI 16384
#define S_BLO 20480
#define S_BUF 24576          // elems per stage
#define SMEM_STEP 147456     // 3 stages x 48KB

// --- k_enc buffers (M=128): 4 arrays of 128x32 = 32KB ---
#define ARR 4096
#define BUFSZ 16384
#define SMEM_ENC 98304       // 3 stages x 32KB

// GM=true: B smem row c = ni*32 + wn*8 + qr (gate-major cols)
// GM=false: c = wn*32 + ni*8 + qr (plain cols)
// B hi+lo merged into one ldsm4 via lane groups. Product-outer MMA order.
template <bool GM>
__device__ __forceinline__ void compute_chunk(const __nv_bfloat16* ahi, const __nv_bfloat16* alo,
                                              const __nv_bfloat16* bhi, const __nv_bfloat16* blo,
                                              float acc[4][4][4], int wm, int wn, int lane) {
  const int lr = lane & 7;
  const int arofs = ((lane >> 3) & 1) * 8;
  const int akb = (lane >> 4) * 8;
  const int bksel = (lane >> 3) & 1;
  const __nv_bfloat16* bbase = (lane >= 16) ? blo : bhi;
#pragma unroll
  for (int kk = 0; kk < 32; kk += 16) {
    unsigned ah[4][4], al[4][4], bb[4][4];
#pragma unroll
    for (int mi = 0; mi < 4; mi++) {
      int r = wm * 64 + mi * 16 + lr + arofs;
      int s = (kk + akb) >> 3;
      ldsm4(ah[mi], ahi + SWZ(r, s));
      ldsm4(al[mi], alo + SWZ(r, s));
    }
#pragma unroll
    for (int ni = 0; ni < 4; ni++) {
      int c = (GM ? ni * 32 + wn * 8 : wn * 32 + ni * 8) + lr;
      ldsm4(bb[ni], bbase + SWZ(c, (kk >> 3) + bksel));
    }
#pragma unroll
    for (int mi = 0; mi < 4; mi++)
#pragma unroll
      for (int ni = 0; ni < 4; ni++) mma16816(acc[mi][ni], ah[mi], &bb[ni][0]);
#pragma unroll
    for (int mi = 0; mi < 4; mi++)
#pragma unroll
      for (int ni = 0; ni < 4; ni++) mma16816(acc[mi][ni], ah[mi], &bb[ni][2]);
#pragma unroll
    for (int mi = 0; mi < 4; mi++)
#pragma unroll
      for (int ni = 0; ni < 4; ni++) mma16816(acc[mi][ni], al[mi], &bb[ni][0]);
  }
}

__device__ __forceinline__ void st_split2(__nv_bfloat16* ph, __nv_bfloat16* pl,
                                          float x, float y) {
  __nv_bfloat16 xh = __float2bfloat16(x), yh = __float2bfloat16(y);
  __nv_bfloat162 t; t.x = xh; t.y = yh;
  *(__nv_bfloat162*)ph = t;
  __nv_bfloat162 u;
  u.x = __float2bfloat16(x - __bfloat162float(xh));
  u.y = __float2bfloat16(y - __bfloat162float(yh));
  *(__nv_bfloat162*)pl = u;
}

// ---------------------------------------------------------------------------
// Split kernels (run every call; deterministic)
// ---------------------------------------------------------------------------
__global__ void k_split_x(const float* __restrict__ xl, const float* __restrict__ xr) {
  long i = (long)blockIdx.x * NT + threadIdx.x;  // [0, 16777216) float4 groups
  long chain = i >> 23;
  long j = i & 8388607;
  float4 v = *(const float4*)((chain ? xr : xl) + j * 4);
  long o = chain * 33554432 + j * 4;
  float x[4] = {v.x, v.y, v.z, v.w};
  __nv_bfloat162 h0, h1, l0, l1;
  __nv_bfloat16 b0 = __float2bfloat16(x[0]), b1 = __float2bfloat16(x[1]);
  __nv_bfloat16 b2 = __float2bfloat16(x[2]), b3 = __float2bfloat16(x[3]);
  h0.x = b0; h0.y = b1; h1.x = b2; h1.y = b3;
  l0.x = __float2bfloat16(x[0] - __bfloat162float(b0));
  l0.y = __float2bfloat16(x[1] - __bfloat162float(b1));
  l1.x = __float2bfloat16(x[2] - __bfloat162float(b2));
  l1.y = __float2bfloat16(x[3] - __bfloat162float(b3));
  *(__nv_bfloat162*)(g_xs_hi + o) = h0;
  *(__nv_bfloat162*)(g_xs_hi + o + 2) = h1;
  *(__nv_bfloat162*)(g_xs_lo + o) = l0;
  *(__nv_bfloat162*)(g_xs_lo + o + 2) = l1;
}

__global__ void k_split_misc(const float* __restrict__ Whh_l, const float* __restrict__ Whh_r,
                             const float* __restrict__ Wih_l, const float* __restrict__ Wih_r,
                             const float* __restrict__ Wenc, const float* __restrict__ rel,
                             const float* __restrict__ bih_l, const float* __restrict__ bhh_l,
                             const float* __restrict__ bih_r, const float* __restrict__ bhh_r) {
  long idx = (long)blockIdx.x * NT + threadIdx.x;
  if (idx < 1048576) {
    // Wcomb gather: dst (((z*8+strip)*128 + (g*32+jj))*512 + k
    int k = (int)(idx & 511);
    long r2 = idx >> 9;
    int row = (int)(r2 & 127);
    int zs = (int)(r2 >> 7);
    int strip = zs & 7, z = zs >> 3;
    int g = row >> 5, jj = row & 31;
    long wrow = (long)(g * 256 + strip * 32 + jj) * 256;
    float v;
    if (k < 256) v = (z ? Whh_r : Whh_l)[wrow + k];
    else         v = (z ? Wih_r : Wih_l)[wrow + k - 256];
    __nv_bfloat16 h = __float2bfloat16(v);
    g_Wcomb_hi[idx] = h;
    g_Wcomb_lo[idx] = __float2bfloat16(v - __bfloat162float(h));
  } else if (idx < 1196032) {
    long j = idx - 1048576;
    float v = Wenc[j];
    __nv_bfloat16 h = __float2bfloat16(v);
    g_WencS_hi[j] = h;
    g_WencS_lo[j] = __float2bfloat16(v - __bfloat162float(h));
  } else if (idx < 2244608) {
    long j = idx - 1196032;
    float v = rel[j];
    __nv_bfloat16 h = __float2bfloat16(v);
    g_rels_hi[j] = h;
    g_rels_lo[j] = __float2bfloat16(v - __bfloat162float(h));
  } else if (idx < 2246656) {
    long j = idx - 2244608;  // [0,2048)
    int z = (int)(j >> 10);
    int cc = (int)(j & 1023);
    g_bsum[j] = (z ? bih_r[cc] : bih_l[cc]) + (z ? bhh_r[cc] : bhh_l[cc]);
  }
}

// ---------------------------------------------------------------------------
// Fused recurrent step t (0..7): gates = [h_{t-1} | x_t] @ Wcomb^T + bsum.
// grid (strip=8, rowTile=64, z=2), 512 threads. CTA tile M=256 x N=128.
// K=512 = 16 chunks (8 h + 8 x); t=0 skips h chunks. 3-stage cp.async.
// Warps: wm = wid&3 (64-row groups), wn = wid>>2 (gate-major 8-col groups).
// ---------------------------------------------------------------------------
// stage a 256x32 A chunk: 1024 segs per array, 2 per thread
__device__ __forceinline__ void stage_A512(__nv_bfloat16* d, const __nv_bfloat16* s,
                                           long rowBase, int ld, int koff, int tid) {
#pragma unroll
  for (int i = 0; i < 2; i++) {
    int f = tid + i * NTS;
    int row = f >> 2, seg = f & 3;
    cpa16(d + SWZ(row, seg), s + (rowBase + row) * (long)ld + koff + seg * 8);
  }
}
// stage a 128x32 B chunk: 512 segs per array, 1 per thread
__device__ __forceinline__ void stage_B512(__nv_bfloat16* d, const __nv_bfloat16* s,
                                           long rowBase, int ld, int koff, int tid) {
  int row = tid >> 2, seg = tid & 3;
  cpa16(d + SWZ(row, seg), s + (rowBase + row) * (long)ld + koff + seg * 8);
}

__device__ __forceinline__ void step_stage_full(__nv_bfloat16* base, long rowBase,
                                                long bRow, int kc, int t, int z, int tid) {
  if (kc < 8) {
    long off = ((long)z * 2 + (t & 1)) * 4194304;
    stage_A512(base + S_AHI, g_hs_hi + off, rowBase, 256, kc * 32, tid);
    stage_A512(base + S_ALO, g_hs_lo + off, rowBase, 256, kc * 32, tid);
  } else {
    long off = (long)z * 33554432 + t * 256;  // row n -> (n*8+t)*256
    stage_A512(base + S_AHI, g_xs_hi + off, rowBase, 2048, (kc - 8) * 32, tid);
    stage_A512(base + S_ALO, g_xs_lo + off, rowBase, 2048, (kc - 8) * 32, tid);
  }
  stage_B512(base + S_BHI, g_Wcomb_hi, bRow, 512, kc * 32, tid);
  stage_B512(base + S_BLO, g_Wcomb_lo, bRow, 512, kc * 32, tid);
}

__global__ __launch_bounds__(NTS, 1) void k_step(int t) {
  extern __shared__ __nv_bfloat16 sm[];
  const int tid = threadIdx.x;
  const int z = blockIdx.z, strip = blockIdx.x;
  const long rowBase = (long)blockIdx.y * 256;
  __nv_bfloat16* hnh = g_hs_hi + ((long)z * 2 + ((t + 1) & 1)) * 4194304;
  __nv_bfloat16* hnl = g_hs_lo + ((long)z * 2 + ((t + 1) & 1)) * 4194304;
  float* cst = g_c + (long)z * 4194304;
  const long bRow = (long)(z * 8 + strip) * 128;

  const int wid = tid >> 5, lane = tid & 31;
  const int wm = wid & 3, wn = wid >> 2;
  const int qr = lane >> 2, qc = (lane & 3) << 1;

  const int kc0 = (t == 0) ? 8 : 0;   // t=0: x chunks only (h0 = 0)
  const int NK = 16 - kc0;

  float acc[4][4][4];
#pragma unroll
  for (int a = 0; a < 4; a++)
#pragma unroll
    for (int b = 0; b < 4; b++)
#pragma unroll
      for (int q = 0; q < 4; q++) acc[a][b][q] = 0.0f;

  // prologue: stage chunks kc0, kc0+1 into stages 0, 1
  step_stage_full(sm, rowBase, bRow, kc0, t, z, tid);
  CP_COMMIT;
  step_stage_full(sm + S_BUF, rowBase, bRow, kc0 + 1, t, z, tid);
  CP_COMMIT;

  int stg = 0, stg2 = 2;  // stage of chunk i, stage of chunk i+2
  for (int i = 0; i < NK; i++) {
    cp_wait<1>();
    __syncthreads();
    if (i + 2 < NK)
      step_stage_full(sm + stg2 * S_BUF, rowBase, bRow, kc0 + i + 2, t, z, tid);
    CP_COMMIT;
    const __nv_bfloat16* base = sm + stg * S_BUF;
    compute_chunk<true>(base + S_AHI, base + S_ALO, base + S_BHI, base + S_BLO,
                        acc, wm, wn, lane);
    stg = (stg == 2) ? 0 : stg + 1;
    stg2 = (stg2 == 2) ? 0 : stg2 + 1;
  }

  // register epilogue: ni -> gate (i,f,g,o) of j = strip*32 + wn*8 + qc
  const int jloc = strip * 32 + wn * 8 + qc;
  const float* bs = g_bsum + z * 1024;
  const float2 bi2 = *(const float2*)(bs + jloc);
  const float2 bf2 = *(const float2*)(bs + 256 + jloc);
  const float2 bg2 = *(const float2*)(bs + 512 + jloc);
  const float2 bo2 = *(const float2*)(bs + 768 + jloc);
#pragma unroll
  for (int mi = 0; mi < 4; mi++) {
#pragma unroll
    for (int hh = 0; hh < 2; hh++) {
      const long n = rowBase + wm * 64 + mi * 16 + qr + hh * 8;
      float2 cp2 = make_float2(0.0f, 0.0f);
      if (t) cp2 = *(const float2*)(cst + n * 256 + jloc);
      const int b = hh * 2;
      float gi0 = acc[mi][0][b] + bi2.x, gi1 = acc[mi][0][b + 1] + bi2.y;
      float gf0 = acc[mi][1][b] + bf2.x, gf1 = acc[mi][1][b + 1] + bf2.y;
      float gg0 = acc[mi][2][b] + bg2.x, gg1 = acc[mi][2][b + 1] + bg2.y;
      float go0 = acc[mi][3][b] + bo2.x, go1 = acc[mi][3][b + 1] + bo2.y;
      float c0 = fsig(gf0) * cp2.x + fsig(gi0) * ftanh(gg0);
      float c1 = fsig(gf1) * cp2.y + fsig(gi1) * ftanh(gg1);
      *(float2*)(cst + n * 256 + jloc) = make_float2(c0, c1);
      float h0 = fsig(go0) * ftanh(c0);
      float h1 = fsig(go1) * ftanh(c1);
      st_split2(hnh + n * 256 + jloc, hnl + n * 256 + jloc, h0, h1);
    }
  }
}

// ---------------------------------------------------------------------------
// Encoder: out = tanh([hl, hr, rel] @ Wenc^T + benc). grid (colTile=2, rowTile=128)
// 256 threads, tile 128x128. K = 576 = 18 chunks; A source hl -> hr -> rel.
// ---------------------------------------------------------------------------
__device__ __forceinline__ void stage_pair(__nv_bfloat16* d, const __nv_bfloat16* s,
                                           long rowBase, int ld, int koff, int tid) {
#pragma unroll
  for (int i = 0; i < 2; i++) {
    int f = tid + i * NT;
    int row = f >> 2, seg = f & 3;
    cpa16(d + SWZ(row, seg), s + (rowBase + row) * (long)ld + koff + seg * 8);
  }
}

__device__ __forceinline__ void enc_stage_full(__nv_bfloat16* base, long rowBase,
                                               long bRow, int kc, int tid) {
  const __nv_bfloat16 *sh, *sl;
  int ld, koff;
  if (kc < 8)       { sh = g_hs_hi;                sl = g_hs_lo;                ld = 256; koff = kc * 32; }
  else if (kc < 16) { sh = g_hs_hi + 2L * 4194304; sl = g_hs_lo + 2L * 4194304; ld = 256; koff = (kc - 8) * 32; }
  else              { sh = g_rels_hi;              sl = g_rels_lo;              ld = 64;  koff = (kc - 16) * 32; }
  stage_pair(base, sh, rowBase, ld, koff, tid);
  stage_pair(base + ARR, sl, rowBase, ld, koff, tid);
  stage_pair(base + 2 * ARR, g_WencS_hi, bRow, 576, kc * 32, tid);
  stage_pair(base + 3 * ARR, g_WencS_lo, bRow, 576, kc * 32, tid);
}

__global__ __launch_bounds__(NT, 2) void k_enc(const float* __restrict__ benc,
                                               float* __restrict__ out) {
  extern __shared__ __nv_bfloat16 sm[];
  const int tid = threadIdx.x;
  const int colTile = blockIdx.x;
  const long rowBase = (long)blockIdx.y * 128;
  const long bRow = (long)colTile * 128;

  const int wid = tid >> 5, lane = tid & 31;
  const int wm = wid & 1, wn = wid >> 1;
  const int qr = lane >> 2, qc = (lane & 3) << 1;

  float acc[4][4][4];
#pragma unroll
  for (int a = 0; a < 4; a++)
#pragma unroll
    for (int b = 0; b < 4; b++)
#pragma unroll
      for (int q = 0; q < 4; q++) acc[a][b][q] = 0.0f;

  enc_stage_full(sm, rowBase, bRow, 0, tid);
  CP_COMMIT;
  enc_stage_full(sm + BUFSZ, rowBase, bRow, 1, tid);
  CP_COMMIT;

  int stg = 0, stg2 = 2;
  for (int i = 0; i < 18; i++) {
    cp_wait<1>();
    __syncthreads();
    if (i + 2 < 18)
      enc_stage_full(sm + stg2 * BUFSZ, rowBase, bRow, i + 2, tid);
    CP_COMMIT;
    const __nv_bfloat16* base = sm + stg * BUFSZ;
    compute_chunk<false>(base, base + ARR, base + 2 * ARR, base + 3 * ARR, acc, wm, wn, lane);
    stg = (stg == 2) ? 0 : stg + 1;
    stg2 = (stg2 == 2) ? 0 : stg2 + 1;
  }

#pragma unroll
  for (int mi = 0; mi < 4; mi++) {
#pragma unroll
    for (int hh = 0; hh < 2; hh++) {
      long n = rowBase + wm * 64 + mi * 16 + qr + hh * 8;
#pragma unroll
      for (int ni = 0; ni < 4; ni++) {
        int col = colTile * 128 + wn * 32 + ni * 8 + qc;
        float2 b2 = *(const float2*)(benc + col);
        float v0 = ftanh(acc[mi][ni][hh * 2] + b2.x);
        float v1 = ftanh(acc[mi][ni][hh * 2 + 1] + b2.y);
        *(float2*)(out + n * 256 + col) = make_float2(v0, v1);
      }
    }
  }
}

// ---------------------------------------------------------------------------
extern "C" void kernel_launch(void* const* d_in, const int* in_sizes, int n_in,
                              void* d_out, int out_size) {
  (void)in_sizes; (void)n_in; (void)out_size;
  const float* left  = (const float*)d_in[0];
  const float* right = (const float*)d_in[1];
  const float* rel   = (const float*)d_in[2];
  const float* Wih_l = (const float*)d_in[3];
  const float* Whh_l = (const float*)d_in[4];
  const float* bih_l = (const float*)d_in[5];
  const float* bhh_l = (const float*)d_in[6];
  const float* Wih_r = (const float*)d_in[7];
  const float* Whh_r = (const float*)d_in[8];
  const float* bih_r = (const float*)d_in[9];
  const float* bhh_r = (const float*)d_in[10];
  const float* Wenc  = (const float*)d_in[11];
  const float* benc  = (const float*)d_in[12];
  float* out = (float*)d_out;

  cudaFuncSetAttribute(k_step, cudaFuncAttributeMaxDynamicSharedMemorySize, SMEM_STEP);
  cudaFuncSetAttribute(k_enc, cudaFuncAttributeMaxDynamicSharedMemorySize, SMEM_ENC);

  k_split_x<<<65536, NT>>>(left, right);
  k_split_misc<<<8776, NT>>>(Whh_l, Whh_r, Wih_l, Wih_r, Wenc, rel,
                             bih_l, bhh_l, bih_r, bhh_r);
  for (int t = 0; t < 8; t++)
    k_step<<<dim3(8, 64, 2), NTS, SMEM_STEP>>>(t);
  k_enc<<<dim3(2, 128), NT, SMEM_ENC>>>(benc, out);
}

// round 15
// speedup vs baseline: 1.1776x; 1.1776x over previous
#include <cuda_runtime.h>
#include <cuda_bf16.h>
#include <math.h>

// N=16384 nodes, L=8, D=256, H=256, R=64. Gate order i,f,g,o.
// Fused recurrence: gates_t = [h_{t-1} | x_t] @ [Whh | Wih]^T + b (K=512 GEMM
// per step; t=0 uses x-only K=256 since h0=0). mma.sync bf16 hi/lo split
// (3 products), XOR-swizzled smem, 2-stage cp.async (64KB/CTA, 2 CTAs/SM),
// merged-B ldmatrix, software-pipelined A-fragment loads (mi-granular
// prefetch interleaved with MMA issue), register epilogues.

#define NT 256

// ------------------------- device scratch (no allocs) -----------------------
__device__ float g_c[8388608];               // [2][16384][256] cell state fp32
__device__ __nv_bfloat16 g_hs_hi[16777216];  // [2 lstm][2 buf][16384][256]
__device__ __nv_bfloat16 g_hs_lo[16777216];
__device__ __nv_bfloat16 g_xs_hi[67108864];  // [2 chain][16384*8 (n*8+l)][256]
__device__ __nv_bfloat16 g_xs_lo[67108864];
__device__ __nv_bfloat16 g_Wcomb_hi[1048576]; // [2][8 strip][128(g*32+jj)][512(Whh|Wih)]
__device__ __nv_bfloat16 g_Wcomb_lo[1048576];
__device__ __nv_bfloat16 g_WencS_hi[147456];  // [256][576]
__device__ __nv_bfloat16 g_WencS_lo[147456];
__device__ __nv_bfloat16 g_rels_hi[1048576];  // [16384][64]
__device__ __nv_bfloat16 g_rels_lo[1048576];
__device__ float g_bsum[2048];                // [2][1024] bih+bhh

// ------------------------------- helpers ------------------------------------
__device__ __forceinline__ float fsig(float x) {
  return __fdividef(1.0f, 1.0f + __expf(-x));
}
__device__ __forceinline__ float ftanh(float x) {
  return 2.0f * __fdividef(1.0f, 1.0f + __expf(-2.0f * x)) - 1.0f;
}

__device__ __forceinline__ void mma16816(float* d, const unsigned* a, const unsigned* b) {
  asm volatile(
      "mma.sync.aligned.m16n8k16.row.col.f32.bf16.bf16.f32 "
      "{%0,%1,%2,%3}, {%4,%5,%6,%7}, {%8,%9}, {%0,%1,%2,%3};\n"
      : "+f"(d[0]), "+f"(d[1]), "+f"(d[2]), "+f"(d[3])
      : "r"(a[0]), "r"(a[1]), "r"(a[2]), "r"(a[3]), "r"(b[0]), "r"(b[1]));
}
__device__ __forceinline__ void ldsm4(unsigned* r, const __nv_bfloat16* p) {
  unsigned a = (unsigned)__cvta_generic_to_shared(p);
  asm volatile("ldmatrix.sync.aligned.m8n8.x4.shared.b16 {%0,%1,%2,%3}, [%4];\n"
               : "=r"(r[0]), "=r"(r[1]), "=r"(r[2]), "=r"(r[3]) : "r"(a));
}
__device__ __forceinline__ void cpa16(void* dst, const void* src) {
  unsigned s = (unsigned)__cvta_generic_to_shared(dst);
  asm volatile("cp.async.cg.shared.global [%0], [%1], 16;\n" :: "r"(s), "l"(src));
}
#define CP_COMMIT asm volatile("cp.async.commit_group;\n")
template <int N>
__device__ __forceinline__ void cp_wait() {
  asm volatile("cp.async.wait_group %0;\n" :: "n"(N));
}

// XOR-swizzled smem layout: array [128 rows][32 bf16] (64B rows, no pad).
// Element offset for (row r, 16B-seg s in 0..3): r*32 + ((s ^ ((r>>1)&3))<<3).
#define SWZ(r, s) ((r) * 32 + ((((s) ^ (((r) >> 1) & 3))) << 3))
#define ARR 4096     // 128*32 elems per array
#define BUFSZ 16384  // 4*ARR elems per buffer (32KB)
#define SMEM_BYTES 65536  // 2 stages x 32KB

// stage one 128x32 bf16 chunk: 512 16B segs, 2 per thread
__device__ __forceinline__ void stage_pair(__nv_bfloat16* d, const __nv_bfloat16* s,
                                           long rowBase, int ld, int koff, int tid) {
#pragma unroll
  for (int i = 0; i < 2; i++) {
    int f = tid + i * NT;
    int row = f >> 2, seg = f & 3;
    cpa16(d + SWZ(row, seg), s + (rowBase + row) * (long)ld + koff + seg * 8);
  }
}

// GM=true: B smem row c = ni*32 + wn*8 + qr (gate-major cols)
// GM=false: c = wn*32 + ni*8 + qr (plain cols)
// B hi+lo merged into one ldsm4 via lane groups (0-7: bhi/k, 8-15: bhi/k+8,
// 16-23: blo/k, 24-31: blo/k+8).
// A fragments software-pipelined at mi granularity: prefetch A(mi+1) before
// issuing mi's 12 MMAs, so LDS and HMMA interleave within each warp.
template <bool GM>
__device__ __forceinline__ void compute_chunk(const __nv_bfloat16* ahi, const __nv_bfloat16* alo,
                                              const __nv_bfloat16* bhi, const __nv_bfloat16* blo,
                                              float acc[4][4][4], int wm, int wn, int lane) {
  const int lr = lane & 7;
  const int arofs = ((lane >> 3) & 1) * 8;
  const int akb = (lane >> 4) * 8;
  const int bksel = (lane >> 3) & 1;
  const __nv_bfloat16* bbase = (lane >= 16) ? blo : bhi;
#pragma unroll
  for (int kk = 0; kk < 32; kk += 16) {
    unsigned bb[4][4];
#pragma unroll
    for (int ni = 0; ni < 4; ni++) {
      int c = (GM ? ni * 32 + wn * 8 : wn * 32 + ni * 8) + lr;
      ldsm4(bb[ni], bbase + SWZ(c, (kk >> 3) + bksel));
    }
    const int s = (kk + akb) >> 3;
    unsigned ah[2][4], al[2][4];
    {
      int r = wm * 64 + lr + arofs;
      ldsm4(ah[0], ahi + SWZ(r, s));
      ldsm4(al[0], alo + SWZ(r, s));
    }
#pragma unroll
    for (int mi = 0; mi < 4; mi++) {
      const int cur = mi & 1, nxt = cur ^ 1;
      if (mi < 3) {  // prefetch next mi's A fragments
        int r = wm * 64 + (mi + 1) * 16 + lr + arofs;
        ldsm4(ah[nxt], ahi + SWZ(r, s));
        ldsm4(al[nxt], alo + SWZ(r, s));
      }
      // 12 MMAs for this mi; same-acc separation = 4 issues
#pragma unroll
      for (int ni = 0; ni < 4; ni++) mma16816(acc[mi][ni], ah[cur], &bb[ni][0]);
#pragma unroll
      for (int ni = 0; ni < 4; ni++) mma16816(acc[mi][ni], ah[cur], &bb[ni][2]);
#pragma unroll
      for (int ni = 0; ni < 4; ni++) mma16816(acc[mi][ni], al[cur], &bb[ni][0]);
    }
  }
}

__device__ __forceinline__ void st_split2(__nv_bfloat16* ph, __nv_bfloat16* pl,
                                          float x, float y) {
  __nv_bfloat16 xh = __float2bfloat16(x), yh = __float2bfloat16(y);
  __nv_bfloat162 t; t.x = xh; t.y = yh;
  *(__nv_bfloat162*)ph = t;
  __nv_bfloat162 u;
  u.x = __float2bfloat16(x - __bfloat162float(xh));
  u.y = __float2bfloat16(y - __bfloat162float(yh));
  *(__nv_bfloat162*)pl = u;
}

// ---------------------------------------------------------------------------
// Split kernels (run every call; deterministic)
// ---------------------------------------------------------------------------
__global__ void k_split_x(const float* __restrict__ xl, const float* __restrict__ xr) {
  long i = (long)blockIdx.x * NT + threadIdx.x;  // [0, 16777216) float4 groups
  long chain = i >> 23;
  long j = i & 8388607;
  float4 v = *(const float4*)((chain ? xr : xl) + j * 4);
  long o = chain * 33554432 + j * 4;
  float x[4] = {v.x, v.y, v.z, v.w};
  __nv_bfloat162 h0, h1, l0, l1;
  __nv_bfloat16 b0 = __float2bfloat16(x[0]), b1 = __float2bfloat16(x[1]);
  __nv_bfloat16 b2 = __float2bfloat16(x[2]), b3 = __float2bfloat16(x[3]);
  h0.x = b0; h0.y = b1; h1.x = b2; h1.y = b3;
  l0.x = __float2bfloat16(x[0] - __bfloat162float(b0));
  l0.y = __float2bfloat16(x[1] - __bfloat162float(b1));
  l1.x = __float2bfloat16(x[2] - __bfloat162float(b2));
  l1.y = __float2bfloat16(x[3] - __bfloat162float(b3));
  *(__nv_bfloat162*)(g_xs_hi + o) = h0;
  *(__nv_bfloat162*)(g_xs_hi + o + 2) = h1;
  *(__nv_bfloat162*)(g_xs_lo + o) = l0;
  *(__nv_bfloat162*)(g_xs_lo + o + 2) = l1;
}

__global__ void k_split_misc(const float* __restrict__ Whh_l, const float* __restrict__ Whh_r,
                             const float* __restrict__ Wih_l, const float* __restrict__ Wih_r,
                             const float* __restrict__ Wenc, const float* __restrict__ rel,
                             const float* __restrict__ bih_l, const float* __restrict__ bhh_l,
                             const float* __restrict__ bih_r, const float* __restrict__ bhh_r) {
  long idx = (long)blockIdx.x * NT + threadIdx.x;
  if (idx < 1048576) {
    // Wcomb gather: dst (((z*8+strip)*128 + (g*32+jj))*512 + k
    int k = (int)(idx & 511);
    long r2 = idx >> 9;
    int row = (int)(r2 & 127);
    int zs = (int)(r2 >> 7);
    int strip = zs & 7, z = zs >> 3;
    int g = row >> 5, jj = row & 31;
    long wrow = (long)(g * 256 + strip * 32 + jj) * 256;
    float v;
    if (k < 256) v = (z ? Whh_r : Whh_l)[wrow + k];
    else         v = (z ? Wih_r : Wih_l)[wrow + k - 256];
    __nv_bfloat16 h = __float2bfloat16(v);
    g_Wcomb_hi[idx] = h;
    g_Wcomb_lo[idx] = __float2bfloat16(v - __bfloat162float(h));
  } else if (idx < 1196032) {
    long j = idx - 1048576;
    float v = Wenc[j];
    __nv_bfloat16 h = __float2bfloat16(v);
    g_WencS_hi[j] = h;
    g_WencS_lo[j] = __float2bfloat16(v - __bfloat162float(h));
  } else if (idx < 2244608) {
    long j = idx - 1196032;
    float v = rel[j];
    __nv_bfloat16 h = __float2bfloat16(v);
    g_rels_hi[j] = h;
    g_rels_lo[j] = __float2bfloat16(v - __bfloat162float(h));
  } else if (idx < 2246656) {
    long j = idx - 2244608;  // [0,2048)
    int z = (int)(j >> 10);
    int cc = (int)(j & 1023);
    g_bsum[j] = (z ? bih_r[cc] : bih_l[cc]) + (z ? bhh_r[cc] : bhh_l[cc]);
  }
}

// ---------------------------------------------------------------------------
// Fused recurrent step t (0..7): gates = [h_{t-1} | x_t] @ Wcomb^T + bsum.
// grid (strip=8, rowTile=128, z=2), 256 threads, 2 CTAs/SM. K=512 = 16 chunks
// (8 h + 8 x); t=0 skips the h chunks (h0=0). 2-stage cp.async pipeline.
// Gate-major fragment map (ni=gate): register cell-update epilogue.
// ---------------------------------------------------------------------------
__device__ __forceinline__ void step_stage_full(__nv_bfloat16* base, long rowBase,
                                                long bRow, int kc, int t, int z, int tid) {
  if (kc < 8) {
    long off = ((long)z * 2 + (t & 1)) * 4194304;
    stage_pair(base, g_hs_hi + off, rowBase, 256, kc * 32, tid);
    stage_pair(base + ARR, g_hs_lo + off, rowBase, 256, kc * 32, tid);
  } else {
    long off = (long)z * 33554432 + t * 256;  // row n -> (n*8+t)*256
    stage_pair(base, g_xs_hi + off, rowBase, 2048, (kc - 8) * 32, tid);
    stage_pair(base + ARR, g_xs_lo + off, rowBase, 2048, (kc - 8) * 32, tid);
  }
  stage_pair(base + 2 * ARR, g_Wcomb_hi, bRow, 512, kc * 32, tid);
  stage_pair(base + 3 * ARR, g_Wcomb_lo, bRow, 512, kc * 32, tid);
}

__global__ __launch_bounds__(NT, 2) void k_step(int t) {
  extern __shared__ __nv_bfloat16 sm[];
  const int tid = threadIdx.x;
  const int z = blockIdx.z, strip = blockIdx.x;
  const long rowBase = (long)blockIdx.y * 128;
  __nv_bfloat16* hnh = g_hs_hi + ((long)z * 2 + ((t + 1) & 1)) * 4194304;
  __nv_bfloat16* hnl = g_hs_lo + ((long)z * 2 + ((t + 1) & 1)) * 4194304;
  float* cst = g_c + (long)z * 4194304;
  const long bRow = (long)(z * 8 + strip) * 128;

  const int wid = tid >> 5, lane = tid & 31;
  const int wm = wid & 1, wn = wid >> 1;
  const int qr = lane >> 2, qc = (lane & 3) << 1;

  const int kc0 = (t == 0) ? 8 : 0;   // t=0: x chunks only (h0 = 0)
  const int NK = 16 - kc0;

  float acc[4][4][4];
#pragma unroll
  for (int a = 0; a < 4; a++)
#pragma unroll
    for (int b = 0; b < 4; b++)
#pragma unroll
      for (int q = 0; q < 4; q++) acc[a][b][q] = 0.0f;

  step_stage_full(sm, rowBase, bRow, kc0, t, z, tid);
  CP_COMMIT;

  for (int i = 0; i < NK; i++) {
    cp_wait<0>();
    __syncthreads();
    if (i + 1 < NK) {
      step_stage_full(sm + ((i + 1) & 1) * BUFSZ, rowBase, bRow, kc0 + i + 1, t, z, tid);
      CP_COMMIT;
    }
    const __nv_bfloat16* base = sm + (i & 1) * BUFSZ;
    compute_chunk<true>(base, base + ARR, base + 2 * ARR, base + 3 * ARR, acc, wm, wn, lane);
  }

  // register epilogue: ni -> gate (i,f,g,o) of j = strip*32 + wn*8 + qc
  const int jloc = strip * 32 + wn * 8 + qc;
  const float* bs = g_bsum + z * 1024;
  const float2 bi2 = *(const float2*)(bs + jloc);
  const float2 bf2 = *(const float2*)(bs + 256 + jloc);
  const float2 bg2 = *(const float2*)(bs + 512 + jloc);
  const float2 bo2 = *(const float2*)(bs + 768 + jloc);
#pragma unroll
  for (int mi = 0; mi < 4; mi++) {
#pragma unroll
    for (int hh = 0; hh < 2; hh++) {
      const long n = rowBase + wm * 64 + mi * 16 + qr + hh * 8;
      float2 cp2 = make_float2(0.0f, 0.0f);
      if (t) cp2 = *(const float2*)(cst + n * 256 + jloc);
      const int b = hh * 2;
      float gi0 = acc[mi][0][b] + bi2.x, gi1 = acc[mi][0][b + 1] + bi2.y;
      float gf0 = acc[mi][1][b] + bf2.x, gf1 = acc[mi][1][b + 1] + bf2.y;
      float gg0 = acc[mi][2][b] + bg2.x, gg1 = acc[mi][2][b + 1] + bg2.y;
      float go0 = acc[mi][3][b] + bo2.x, go1 = acc[mi][3][b + 1] + bo2.y;
      float c0 = fsig(gf0) * cp2.x + fsig(gi0) * ftanh(gg0);
      float c1 = fsig(gf1) * cp2.y + fsig(gi1) * ftanh(gg1);
      *(float2*)(cst + n * 256 + jloc) = make_float2(c0, c1);
      float h0 = fsig(go0) * ftanh(c0);
      float h1 = fsig(go1) * ftanh(c1);
      st_split2(hnh + n * 256 + jloc, hnl + n * 256 + jloc, h0, h1);
    }
  }
}

// ---------------------------------------------------------------------------
// Encoder: out = tanh([hl, hr, rel] @ Wenc^T + benc). grid (colTile=2, rowTile=128)
// 256 threads, tile 128x128. K = 576 = 18 chunks; A source hl -> hr -> rel.
// ---------------------------------------------------------------------------
__device__ __forceinline__ void enc_stage_full(__nv_bfloat16* base, long rowBase,
                                               long bRow, int kc, int tid) {
  const __nv_bfloat16 *sh, *sl;
  int ld, koff;
  if (kc < 8)       { sh = g_hs_hi;                sl = g_hs_lo;                ld = 256; koff = kc * 32; }
  else if (kc < 16) { sh = g_hs_hi + 2L * 4194304; sl = g_hs_lo + 2L * 4194304; ld = 256; koff = (kc - 8) * 32; }
  else              { sh = g_rels_hi;              sl = g_rels_lo;              ld = 64;  koff = (kc - 16) * 32; }
  stage_pair(base, sh, rowBase, ld, koff, tid);
  stage_pair(base + ARR, sl, rowBase, ld, koff, tid);
  stage_pair(base + 2 * ARR, g_WencS_hi, bRow, 576, kc * 32, tid);
  stage_pair(base + 3 * ARR, g_WencS_lo, bRow, 576, kc * 32, tid);
}

__global__ __launch_bounds__(NT, 2) void k_enc(const float* __restrict__ benc,
                                               float* __restrict__ out) {
  extern __shared__ __nv_bfloat16 sm[];
  const int tid = threadIdx.x;
  const int colTile = blockIdx.x;
  const long rowBase = (long)blockIdx.y * 128;
  const long bRow = (long)colTile * 128;

  const int wid = tid >> 5, lane = tid & 31;
  const int wm = wid & 1, wn = wid >> 1;
  const int qr = lane >> 2, qc = (lane & 3) << 1;

  float acc[4][4][4];
#pragma unroll
  for (int a = 0; a < 4; a++)
#pragma unroll
    for (int b = 0; b < 4; b++)
#pragma unroll
      for (int q = 0; q < 4; q++) acc[a][b][q] = 0.0f;

  enc_stage_full(sm, rowBase, bRow, 0, tid);
  CP_COMMIT;

  for (int i = 0; i < 18; i++) {
    cp_wait<0>();
    __syncthreads();
    if (i + 1 < 18) {
      enc_stage_full(sm + ((i + 1) & 1) * BUFSZ, rowBase, bRow, i + 1, tid);
      CP_COMMIT;
    }
    const __nv_bfloat16* base = sm + (i & 1) * BUFSZ;
    compute_chunk<false>(base, base + ARR, base + 2 * ARR, base + 3 * ARR, acc, wm, wn, lane);
  }

#pragma unroll
  for (int mi = 0; mi < 4; mi++) {
#pragma unroll
    for (int hh = 0; hh < 2; hh++) {
      long n = rowBase + wm * 64 + mi * 16 + qr + hh * 8;
#pragma unroll
      for (int ni = 0; ni < 4; ni++) {
        int col = colTile * 128 + wn * 32 + ni * 8 + qc;
        float2 b2 = *(const float2*)(benc + col);
        float v0 = ftanh(acc[mi][ni][hh * 2] + b2.x);
        float v1 = ftanh(acc[mi][ni][hh * 2 + 1] + b2.y);
        *(float2*)(out + n * 256 + col) = make_float2(v0, v1);
      }
    }
  }
}

// ---------------------------------------------------------------------------
extern "C" void kernel_launch(void* const* d_in, const int* in_sizes, int n_in,
                              void* d_out, int out_size) {
  (void)in_sizes; (void)n_in; (void)out_size;
  const float* left  = (const float*)d_in[0];
  const float* right = (const float*)d_in[1];
  const float* rel   = (const float*)d_in[2];
  const float* Wih_l = (const float*)d_in[3];
  const float* Whh_l = (const float*)d_in[4];
  const float* bih_l = (const float*)d_in[5];
  const float* bhh_l = (const float*)d_in[6];
  const float* Wih_r = (const float*)d_in[7];
  const float* Whh_r = (const float*)d_in[8];
  const float* bih_r = (const float*)d_in[9];
  const float* bhh_r = (const float*)d_in[10];
  const float* Wenc  = (const float*)d_in[11];
  const float* benc  = (const float*)d_in[12];
  float* out = (float*)d_out;

  cudaFuncSetAttribute(k_step, cudaFuncAttributeMaxDynamicSharedMemorySize, SMEM_BYTES);
  cudaFuncSetAttribute(k_enc, cudaFuncAttributeMaxDynamicSharedMemorySize, SMEM_BYTES);

  k_split_x<<<65536, NT>>>(left, right);
  k_split_misc<<<8776, NT>>>(Whh_l, Whh_r, Wih_l, Wih_r, Wenc, rel,
                             bih_l, bhh_l, bih_r, bhh_r);
  for (int t = 0; t < 8; t++)
    k_step<<<dim3(8, 128, 2), NT, SMEM_BYTES>>>(t);
  k_enc<<<dim3(2, 128), NT, SMEM_BYTES>>>(benc, out);
}